// round 13
// baseline (speedup 1.0000x reference)
#include <cuda_runtime.h>
#include <cuda_bf16.h>
#include <cuda_fp16.h>
#include <cstdint>

// ============================ problem constants ============================
#define NNODES 16384
#define NFEAT  256
#define NHID   64
#define KSPLIT 4
#define KSEG   (NNODES / KSPLIT)   /* 4096 */

// ============================ scratch (device globals) =====================
__device__ __align__(1024) __half g_xw1t[NHID * NNODES];           // XW1^T [hid][node], fp16
__device__ __align__(1024) float  g_part[KSPLIT * NNODES * NHID];  // K-split partials (16 MB)
__device__ __align__(256)  float  g_hw2[NNODES * 2];
__device__ __align__(256)  float  g_h2[NNODES * 2];

// ============================ PTX helpers (base-target only) ===============
__device__ __forceinline__ uint32_t smem_u32(const void* p) {
    uint32_t a;
    asm("{ .reg .u64 t; cvta.to.shared.u64 t, %1; cvt.u32.u64 %0, t; }" : "=r"(a) : "l"(p));
    return a;
}

#define CP_ASYNC16(dst_u32, src_ptr) \
    asm volatile("cp.async.cg.shared.global [%0], [%1], 16;" \
                 :: "r"(dst_u32), "l"(src_ptr) : "memory")
#define CP_COMMIT()  asm volatile("cp.async.commit_group;" ::: "memory")
#define CP_WAIT_2()  asm volatile("cp.async.wait_group 2;" ::: "memory")

// fp16 MMA m16n8k16, fp32 accumulate (base-target sm_80+)
__device__ __forceinline__ void mma_f16(float* d, const uint32_t* a, const uint32_t* b) {
    asm volatile(
        "mma.sync.aligned.m16n8k16.row.col.f32.f16.f16.f32 "
        "{%0,%1,%2,%3}, {%4,%5,%6,%7}, {%8,%9}, {%0,%1,%2,%3};"
        : "+f"(d[0]), "+f"(d[1]), "+f"(d[2]), "+f"(d[3])
        : "r"(a[0]), "r"(a[1]), "r"(a[2]), "r"(a[3]), "r"(b[0]), "r"(b[1]));
}

// scale float2 by 2^14 (exact integer exponent add; adj >= 0) and pack to half2.
__device__ __forceinline__ uint32_t pack_scale14(float2 f) {
    float x = __uint_as_float(__float_as_uint(f.x) + (14u << 23));
    float y = __uint_as_float(__float_as_uint(f.y) + (14u << 23));
    __half2 h = __floats2half2_rn(x, y);
    return *(uint32_t*)&h;
}
#define SCALE_INV 6.103515625e-05f   /* 2^-14, exact */

// ============================ K0: dummy (ncu slot alignment) ===============
__global__ void k_dummy() {}

// ============================ K1: XW1^T (fp16 out) =========================
__global__ __launch_bounds__(256) void k1_xw1t(const float* __restrict__ x,
                                               const float* __restrict__ W1) {
    extern __shared__ float sm1[];
    float* xs = sm1;              // [64][256]
    float* ws = sm1 + 64 * 256;   // [256][64]
    int tid = threadIdx.x;
    int node0 = blockIdx.x * 64;

    const float4* xsrc = (const float4*)(x + (size_t)node0 * NFEAT);
    float4* xdst = (float4*)xs;
#pragma unroll
    for (int j = 0; j < 16; j++) xdst[tid + j * 256] = xsrc[tid + j * 256];
    const float4* wsrc = (const float4*)W1;
    float4* wdst = (float4*)ws;
#pragma unroll
    for (int j = 0; j < 16; j++) wdst[tid + j * 256] = wsrc[tid + j * 256];
    __syncthreads();

    int i0 = (tid >> 4) * 4;
    int n0 = (tid & 15) * 4;
    float acc[4][4];
#pragma unroll
    for (int a = 0; a < 4; a++)
#pragma unroll
        for (int b = 0; b < 4; b++) acc[a][b] = 0.f;

#pragma unroll 4
    for (int f = 0; f < NFEAT; f++) {
        float4 w = *(const float4*)(ws + f * 64 + n0);
#pragma unroll
        for (int ii = 0; ii < 4; ii++) {
            float xv = xs[(i0 + ii) * NFEAT + f];
            acc[ii][0] = fmaf(xv, w.x, acc[ii][0]);
            acc[ii][1] = fmaf(xv, w.y, acc[ii][1]);
            acc[ii][2] = fmaf(xv, w.z, acc[ii][2]);
            acc[ii][3] = fmaf(xv, w.w, acc[ii][3]);
        }
    }
#pragma unroll
    for (int jj = 0; jj < 4; jj++)
#pragma unroll
        for (int ii = 0; ii < 4; ii++)
            g_xw1t[(size_t)(n0 + jj) * NNODES + node0 + i0 + ii] = __float2half_rn(acc[ii][jj]);
}

// ============================ K2: main GEMM, K-split x4 ====================
// CTA: 128 threads, tile M=64, K=4096 -> grid 1024.
// BK=32, NSTAGE=4 (3 in flight) -> 56 KB smem/CTA -> 4 CTAs/SM = 16 warps/SM.
#define BK        32
#define A_PAD     36                         /* fp32 per A row (pad 32->36) */
#define A_BYTES   (64 * A_PAD * 4)           /* 9216 */
#define B_PAD     40                         /* halves per B row (80 B) */
#define B_BYTES   (64 * B_PAD * 2)           /* 5120 */
#define NSTAGE    4
#define B_BASE    (NSTAGE * A_BYTES)
#define K2_SMEM   (B_BASE + NSTAGE * B_BYTES)   /* 57344 */
#define NITER     (KSEG / BK)                   /* 128 */

__device__ __forceinline__ void k2_load_stage(const float* __restrict__ adj, int row0,
                                              int s, int k0, char* smem, int tid) {
    float* As = (float*)(smem + s * A_BYTES);
    char*  Bs = smem + B_BASE + s * B_BYTES;
#pragma unroll
    for (int j = 0; j < 4; j++) {          // A: 64x32 fp32 = 512 float4
        int sl = tid + j * 128;
        int row = sl >> 3, c = sl & 7;
        CP_ASYNC16(smem_u32(As + row * A_PAD + c * 4),
                   adj + (size_t)(row0 + row) * NNODES + k0 + c * 4);
    }
#pragma unroll
    for (int j = 0; j < 2; j++) {          // B: 64x32 fp16 = 256 16B-chunks
        int sl = tid + j * 128;
        int row = sl >> 2, c = sl & 3;
        CP_ASYNC16(smem_u32(Bs + row * 80 + c * 16),
                   g_xw1t + (size_t)row * NNODES + k0 + c * 8);
    }
}

__global__ __launch_bounds__(128, 4) void k2_gemm(const float* __restrict__ adj) {
    extern __shared__ char smem[];
    int tid = threadIdx.x;
    int lane = tid & 31;
    int w = tid >> 5;           // 0..3
    int g = lane >> 2;          // 0..7
    int t = lane & 3;           // 0..3
    int m0 = blockIdx.x & 255;  // M-tile (64 rows)
    int ks = blockIdx.x >> 8;   // K-split 0..3
    int row0 = m0 * 64;
    int kbase = ks * KSEG;

    float d[8][4];
#pragma unroll
    for (int ni = 0; ni < 8; ni++)
#pragma unroll
        for (int c = 0; c < 4; c++) d[ni][c] = 0.f;

    k2_load_stage(adj, row0, 0, kbase, smem, tid);          CP_COMMIT();
    k2_load_stage(adj, row0, 1, kbase + BK, smem, tid);     CP_COMMIT();
    k2_load_stage(adj, row0, 2, kbase + 2 * BK, smem, tid); CP_COMMIT();

    int s = 0;
#pragma unroll 1
    for (int i = 0; i < NITER; i++) {
        CP_WAIT_2();       // stage i complete (<=2 newer groups pending)
        __syncthreads();

        if (i + 3 < NITER) {
            int sn = s + 3; if (sn >= NSTAGE) sn -= NSTAGE;
            k2_load_stage(adj, row0, sn, kbase + (i + 3) * BK, smem, tid);
        }
        CP_COMMIT();       // one group per iter keeps wait_group counting uniform

        const float* As = (const float*)(smem + s * A_BYTES);
        const __half* Bs = (const __half*)(smem + B_BASE + s * B_BYTES);
#pragma unroll
        for (int kk = 0; kk < 2; kk++) {
            int kb = kk * 16;
            uint32_t a[4], b[8][2];
            {
                const float* ap = As + (w * 16 + g) * A_PAD + kb + 2 * t;
                float2 f0 = *(const float2*)(ap);
                float2 f1 = *(const float2*)(ap + 8 * A_PAD);
                float2 f2 = *(const float2*)(ap + 8);
                float2 f3 = *(const float2*)(ap + 8 * A_PAD + 8);
                a[0] = pack_scale14(f0);
                a[1] = pack_scale14(f1);
                a[2] = pack_scale14(f2);
                a[3] = pack_scale14(f3);
            }
#pragma unroll
            for (int ni = 0; ni < 8; ni++) {
                const __half* bp = Bs + (ni * 8 + g) * B_PAD + kb + 2 * t;
                b[ni][0] = *(const uint32_t*)(bp);
                b[ni][1] = *(const uint32_t*)(bp + 8);
            }
#pragma unroll
            for (int ni = 0; ni < 8; ni++)
                mma_f16(d[ni], a, b[ni]);
        }
        if (++s == NSTAGE) s = 0;
    }

    // store raw (still x2^14-scaled) partials; K2b de-scales.
    float* base = g_part + (size_t)ks * NNODES * NHID;
    int r0 = row0 + w * 16 + g;
#pragma unroll
    for (int ni = 0; ni < 8; ni++) {
        int col = ni * 8 + 2 * t;
        *(float2*)(base + (size_t)r0 * NHID + col)       = make_float2(d[ni][0], d[ni][1]);
        *(float2*)(base + (size_t)(r0 + 8) * NHID + col) = make_float2(d[ni][2], d[ni][3]);
    }
}

// ============================ K2b: reduce + relu + @W2 =====================
__global__ __launch_bounds__(256) void k2b_reduce(const float* __restrict__ b1,
                                                  const float* __restrict__ W2) {
    __shared__ float sb1[64], sW2[128];
    int tid = threadIdx.x;
    if (tid < 64) sb1[tid] = b1[tid];
    if (tid < 128) sW2[tid] = W2[tid];
    __syncthreads();

    int row = blockIdx.x * 256 + tid;
    const float4* p0 = (const float4*)(g_part + (size_t)row * NHID);
    const float4* p1 = (const float4*)(g_part + (size_t)(NNODES + row) * NHID);
    const float4* p2 = (const float4*)(g_part + (size_t)(2 * NNODES + row) * NHID);
    const float4* p3 = (const float4*)(g_part + (size_t)(3 * NNODES + row) * NHID);

    float a0 = 0.f, a1 = 0.f;
#pragma unroll
    for (int c4 = 0; c4 < 16; c4++) {
        float4 v0 = p0[c4], v1 = p1[c4], v2 = p2[c4], v3 = p3[c4];
        float sv[4] = {v0.x + v1.x + v2.x + v3.x, v0.y + v1.y + v2.y + v3.y,
                       v0.z + v1.z + v2.z + v3.z, v0.w + v1.w + v2.w + v3.w};
#pragma unroll
        for (int e = 0; e < 4; e++) {
            int col = c4 * 4 + e;
            float h = fmaxf(fmaf(sv[e], SCALE_INV, sb1[col]), 0.f);
            a0 = fmaf(h, sW2[2 * col + 0], a0);
            a1 = fmaf(h, sW2[2 * col + 1], a1);
        }
    }
    g_hw2[2 * row + 0] = a0;
    g_hw2[2 * row + 1] = a1;
}

// ============================ K3: adj @ hw2 + b2 ===========================
// No smem: hw2 via __ldg (L1/L2-resident), adj streamed __ldcs.
// 16 rows/CTA (2 rows/warp), grid 1024, 4 CTAs/SM -> 32 warps/SM of MLP.
__global__ __launch_bounds__(256, 4) void k3_spmv(const float* __restrict__ adj,
                                                  const float* __restrict__ b2) {
    int tid = threadIdx.x;
    int wid = tid >> 5, lane = tid & 31;
    int r0 = blockIdx.x * 16 + wid * 2;
    const float4* ap0 = (const float4*)(adj + (size_t)(r0 + 0) * NNODES);
    const float4* ap1 = (const float4*)(adj + (size_t)(r0 + 1) * NNODES);
    const float4* hp  = (const float4*)g_hw2;

    float acc00 = 0.f, acc01 = 0.f, acc10 = 0.f, acc11 = 0.f;

#pragma unroll 1
    for (int q = lane; q < NNODES / 4; q += 64) {
        float4 a00 = __ldcs(ap0 + q);
        float4 a10 = __ldcs(ap1 + q);
        float4 a01 = __ldcs(ap0 + q + 32);
        float4 a11 = __ldcs(ap1 + q + 32);
        float4 h0a = __ldg(hp + 2 * q);
        float4 h0b = __ldg(hp + 2 * q + 1);
        float4 h1a = __ldg(hp + 2 * (q + 32));
        float4 h1b = __ldg(hp + 2 * (q + 32) + 1);

        acc00 = fmaf(a00.x, h0a.x, acc00);
        acc01 = fmaf(a00.x, h0a.y, acc01);
        acc10 = fmaf(a10.x, h0a.x, acc10);
        acc11 = fmaf(a10.x, h0a.y, acc11);
        acc00 = fmaf(a00.y, h0a.z, acc00);
        acc01 = fmaf(a00.y, h0a.w, acc01);
        acc10 = fmaf(a10.y, h0a.z, acc10);
        acc11 = fmaf(a10.y, h0a.w, acc11);
        acc00 = fmaf(a00.z, h0b.x, acc00);
        acc01 = fmaf(a00.z, h0b.y, acc01);
        acc10 = fmaf(a10.z, h0b.x, acc10);
        acc11 = fmaf(a10.z, h0b.y, acc11);
        acc00 = fmaf(a00.w, h0b.z, acc00);
        acc01 = fmaf(a00.w, h0b.w, acc01);
        acc10 = fmaf(a10.w, h0b.z, acc10);
        acc11 = fmaf(a10.w, h0b.w, acc11);

        acc00 = fmaf(a01.x, h1a.x, acc00);
        acc01 = fmaf(a01.x, h1a.y, acc01);
        acc10 = fmaf(a11.x, h1a.x, acc10);
        acc11 = fmaf(a11.x, h1a.y, acc11);
        acc00 = fmaf(a01.y, h1a.z, acc00);
        acc01 = fmaf(a01.y, h1a.w, acc01);
        acc10 = fmaf(a11.y, h1a.z, acc10);
        acc11 = fmaf(a11.y, h1a.w, acc11);
        acc00 = fmaf(a01.z, h1b.x, acc00);
        acc01 = fmaf(a01.z, h1b.y, acc01);
        acc10 = fmaf(a11.z, h1b.x, acc10);
        acc11 = fmaf(a11.z, h1b.y, acc11);
        acc00 = fmaf(a01.w, h1b.z, acc00);
        acc01 = fmaf(a01.w, h1b.w, acc01);
        acc10 = fmaf(a11.w, h1b.z, acc10);
        acc11 = fmaf(a11.w, h1b.w, acc11);
    }

#pragma unroll
    for (int sft = 16; sft; sft >>= 1) {
        acc00 += __shfl_xor_sync(0xffffffffu, acc00, sft);
        acc01 += __shfl_xor_sync(0xffffffffu, acc01, sft);
        acc10 += __shfl_xor_sync(0xffffffffu, acc10, sft);
        acc11 += __shfl_xor_sync(0xffffffffu, acc11, sft);
    }
    if (lane == 0) {
        float bb0 = b2[0], bb1 = b2[1];
        g_h2[2 * r0 + 0] = acc00 + bb0;
        g_h2[2 * r0 + 1] = acc01 + bb1;
        g_h2[2 * r0 + 2] = acc10 + bb0;
        g_h2[2 * r0 + 3] = acc11 + bb1;
    }
}

// ============================ K4: max-pool + linear ========================
__global__ __launch_bounds__(1024) void k4_final(const float* __restrict__ W3,
                                                 const float* __restrict__ b3,
                                                 float* __restrict__ out) {
    __shared__ float s0[1024], s1[1024];
    int tid = threadIdx.x;
    float m0 = -3.4e38f, m1 = -3.4e38f;
#pragma unroll
    for (int it = 0; it < NNODES / 1024; it++) {
        float2 v = *(const float2*)(g_h2 + 2 * (it * 1024 + tid));
        m0 = fmaxf(m0, v.x);
        m1 = fmaxf(m1, v.y);
    }
    s0[tid] = m0; s1[tid] = m1;
    __syncthreads();
#pragma unroll
    for (int s = 512; s; s >>= 1) {
        if (tid < s) {
            s0[tid] = fmaxf(s0[tid], s0[tid + s]);
            s1[tid] = fmaxf(s1[tid], s1[tid + s]);
        }
        __syncthreads();
    }
    if (tid == 0) out[0] = s0[0] * W3[0] + s1[0] * W3[1] + b3[0];
}

// ============================ launch =======================================
extern "C" void kernel_launch(void* const* d_in, const int* in_sizes, int n_in,
                              void* d_out, int out_size) {
    const float* x   = (const float*)d_in[0];
    const float* adj = (const float*)d_in[1];
    const float* W1  = (const float*)d_in[2];
    const float* b1  = (const float*)d_in[3];
    const float* W2  = (const float*)d_in[4];
    const float* b2  = (const float*)d_in[5];
    const float* W3  = (const float*)d_in[6];
    const float* b3  = (const float*)d_in[7];
    float* out = (float*)d_out;

    (void)in_sizes; (void)n_in; (void)out_size;

    cudaFuncSetAttribute(k1_xw1t, cudaFuncAttributeMaxDynamicSharedMemorySize, 131072);
    cudaFuncSetAttribute(k2_gemm, cudaFuncAttributeMaxDynamicSharedMemorySize, K2_SMEM);

    // two dummies put ncu's capture slot (our 4th launch) on k2_gemm
    k_dummy<<<1, 32>>>();
    k_dummy<<<1, 32>>>();
    k1_xw1t<<<NNODES / 64, 256, 131072>>>(x, W1);
    k2_gemm<<<256 * KSPLIT, 128, K2_SMEM>>>(adj);
    k2b_reduce<<<NNODES / 256, 256>>>(b1, W2);
    k3_spmv<<<NNODES / 16, 256>>>(adj, b2);
    k4_final<<<1, 1024>>>(W3, b3, out);
}

// round 15
// speedup vs baseline: 1.3804x; 1.3804x over previous
#include <cuda_runtime.h>
#include <cuda_bf16.h>
#include <cuda_fp16.h>
#include <cstdint>

// ============================ problem constants ============================
#define NNODES 16384
#define NFEAT  256
#define NHID   64
#define KSPLIT 4
#define KSEG   (NNODES / KSPLIT)   /* 4096 */

// ============================ scratch (device globals) =====================
// XW1^T in mma.sync fragment order:
//   [kg = k/16][ni4 = ni/2][lane][16B], 2 KB per kg, 2 MB total.
//   chunk for (kg, ni4, lane): halves
//     [ni=2*ni4  ][reg0: B[n][16kg+2t],B[n][16kg+2t+1]][reg1: B[n][16kg+8+2t],+1]
//     [ni=2*ni4+1][reg0][reg1]            (n = ni*8 + g, lane = g*4 + t)
__device__ __align__(1024) __half g_xw1f[NHID * NNODES];
__device__ __align__(1024) float  g_part[KSPLIT * NNODES * NHID];  // K-split partials (16 MB)
__device__ __align__(256)  float  g_hw2[NNODES * 2];
__device__ __align__(256)  float  g_h2[NNODES * 2];

// ============================ PTX helpers (base-target only) ===============
__device__ __forceinline__ uint32_t smem_u32(const void* p) {
    uint32_t a;
    asm("{ .reg .u64 t; cvta.to.shared.u64 t, %1; cvt.u32.u64 %0, t; }" : "=r"(a) : "l"(p));
    return a;
}

#define CP_ASYNC16(dst_u32, src_ptr) \
    asm volatile("cp.async.cg.shared.global [%0], [%1], 16;" \
                 :: "r"(dst_u32), "l"(src_ptr) : "memory")
#define CP_COMMIT()  asm volatile("cp.async.commit_group;" ::: "memory")
#define CP_WAIT_2()  asm volatile("cp.async.wait_group 2;" ::: "memory")

// fp16 MMA m16n8k16, fp32 accumulate (base-target sm_80+)
__device__ __forceinline__ void mma_f16(float* d, const uint32_t* a, uint32_t b0, uint32_t b1) {
    asm volatile(
        "mma.sync.aligned.m16n8k16.row.col.f32.f16.f16.f32 "
        "{%0,%1,%2,%3}, {%4,%5,%6,%7}, {%8,%9}, {%0,%1,%2,%3};"
        : "+f"(d[0]), "+f"(d[1]), "+f"(d[2]), "+f"(d[3])
        : "r"(a[0]), "r"(a[1]), "r"(a[2]), "r"(a[3]), "r"(b0), "r"(b1));
}

// scale float2 by 2^14 (exact integer exponent add; adj >= 0) and pack to half2.
__device__ __forceinline__ uint32_t pack_scale14(float2 f) {
    float x = __uint_as_float(__float_as_uint(f.x) + (14u << 23));
    float y = __uint_as_float(__float_as_uint(f.y) + (14u << 23));
    __half2 h = __floats2half2_rn(x, y);
    return *(uint32_t*)&h;
}
#define SCALE_INV 6.103515625e-05f   /* 2^-14, exact */

// ============================ K0: dummy (ncu slot alignment) ===============
__global__ void k_dummy() {}

// ============================ K1: XW1^T -> fragment layout =================
__global__ __launch_bounds__(256) void k1_xw1t(const float* __restrict__ x,
                                               const float* __restrict__ W1) {
    extern __shared__ float sm1[];
    float* xs = sm1;              // [64][256]
    float* ws = sm1 + 64 * 256;   // [256][64]
    int tid = threadIdx.x;
    int node0 = blockIdx.x * 64;

    const float4* xsrc = (const float4*)(x + (size_t)node0 * NFEAT);
    float4* xdst = (float4*)xs;
#pragma unroll
    for (int j = 0; j < 16; j++) xdst[tid + j * 256] = xsrc[tid + j * 256];
    const float4* wsrc = (const float4*)W1;
    float4* wdst = (float4*)ws;
#pragma unroll
    for (int j = 0; j < 16; j++) wdst[tid + j * 256] = wsrc[tid + j * 256];
    __syncthreads();

    int i0 = (tid >> 4) * 4;
    int n0 = (tid & 15) * 4;
    float acc[4][4];
#pragma unroll
    for (int a = 0; a < 4; a++)
#pragma unroll
        for (int b = 0; b < 4; b++) acc[a][b] = 0.f;

#pragma unroll 4
    for (int f = 0; f < NFEAT; f++) {
        float4 w = *(const float4*)(ws + f * 64 + n0);
#pragma unroll
        for (int ii = 0; ii < 4; ii++) {
            float xv = xs[(i0 + ii) * NFEAT + f];
            acc[ii][0] = fmaf(xv, w.x, acc[ii][0]);
            acc[ii][1] = fmaf(xv, w.y, acc[ii][1]);
            acc[ii][2] = fmaf(xv, w.z, acc[ii][2]);
            acc[ii][3] = fmaf(xv, w.w, acc[ii][3]);
        }
    }
    // scatter into fragment layout
    char* fb = (char*)g_xw1f;
#pragma unroll
    for (int jj = 0; jj < 4; jj++) {
        int h = n0 + jj;              // hid (B row n)
        int g = h & 7, ni = h >> 3;
#pragma unroll
        for (int ii = 0; ii < 4; ii++) {
            int k = node0 + i0 + ii;  // node (B col k)
            int kg = k >> 4, k16 = k & 15;
            int reg = k16 >> 3, rem = k16 & 7, t = rem >> 1, hf = rem & 1;
            size_t off = (size_t)kg * 2048 + (size_t)(ni >> 1) * 512 +
                         (size_t)(g * 4 + t) * 16 + (ni & 1) * 8 + reg * 4 + hf * 2;
            *(__half*)(fb + off) = __float2half_rn(acc[ii][jj]);
        }
    }
}

// ============================ K2: main GEMM, K-split x4 ====================
// CTA: 128 threads, tile M=64, K=4096 -> grid 1024, 2 CTAs/SM (R12 config),
// B in fragment order: 4x LDS.128 per lane per k16, conflict-free.
#define BK        64
#define A_PAD     68                         /* fp32 per A row */
#define A_BYTES   (64 * A_PAD * 4)           /* 17408 */
#define B_BYTES   8192                       /* 4 kg x 2 KB, contiguous */
#define NSTAGE    4
#define B_BASE    (NSTAGE * A_BYTES)
#define K2_SMEM   (B_BASE + NSTAGE * B_BYTES)   /* 102400 */
#define NITER     (KSEG / BK)                   /* 64 */

__device__ __forceinline__ void k2_load_stage(const float* __restrict__ adj, int row0,
                                              int s, int k0, char* smem, int tid) {
    float* As = (float*)(smem + s * A_BYTES);
    char*  Bs = smem + B_BASE + s * B_BYTES;
#pragma unroll
    for (int j = 0; j < 8; j++) {          // A: 64x64 fp32 = 2048 float4
        int sl = tid + j * 128;
        int row = sl >> 4, c = sl & 15;
        CP_ASYNC16(smem_u32(As + row * A_PAD + c * 4),
                   adj + (size_t)(row0 + row) * NNODES + k0 + c * 4);
    }
    const char* bsrc = (const char*)g_xw1f + (size_t)k0 * 128;   // k0/16 * 2048
#pragma unroll
    for (int j = 0; j < 4; j++) {          // B: 8 KB contiguous = 512 chunks
        int sl = tid + j * 128;
        CP_ASYNC16(smem_u32(Bs + sl * 16), bsrc + sl * 16);
    }
}

__global__ __launch_bounds__(128, 2) void k2_gemm(const float* __restrict__ adj) {
    extern __shared__ char smem[];
    int tid = threadIdx.x;
    int lane = tid & 31;
    int w = tid >> 5;           // 0..3
    int g = lane >> 2;          // 0..7
    int t = lane & 3;           // 0..3
    int m0 = blockIdx.x & 255;  // M-tile (64 rows)
    int ks = blockIdx.x >> 8;   // K-split 0..3
    int row0 = m0 * 64;
    int kbase = ks * KSEG;

    float d[8][4];
#pragma unroll
    for (int ni = 0; ni < 8; ni++)
#pragma unroll
        for (int c = 0; c < 4; c++) d[ni][c] = 0.f;

    k2_load_stage(adj, row0, 0, kbase, smem, tid);          CP_COMMIT();
    k2_load_stage(adj, row0, 1, kbase + BK, smem, tid);     CP_COMMIT();
    k2_load_stage(adj, row0, 2, kbase + 2 * BK, smem, tid); CP_COMMIT();

    int s = 0;
#pragma unroll 1
    for (int i = 0; i < NITER; i++) {
        CP_WAIT_2();       // stage i complete (<=2 newer groups pending)
        __syncthreads();

        if (i + 3 < NITER) {
            int sn = s + 3; if (sn >= NSTAGE) sn -= NSTAGE;
            k2_load_stage(adj, row0, sn, kbase + (i + 3) * BK, smem, tid);
        }
        CP_COMMIT();       // one group per iter keeps wait_group counting uniform

        const float* As = (const float*)(smem + s * A_BYTES);
        const char* Bs = smem + B_BASE + s * B_BYTES;
#pragma unroll
        for (int kk = 0; kk < 4; kk++) {
            int kb = kk * 16;
            uint32_t a[4];
            {
                const float* ap = As + (w * 16 + g) * A_PAD + kb + 2 * t;
                float2 f0 = *(const float2*)(ap);
                float2 f1 = *(const float2*)(ap + 8 * A_PAD);
                float2 f2 = *(const float2*)(ap + 8);
                float2 f3 = *(const float2*)(ap + 8 * A_PAD + 8);
                a[0] = pack_scale14(f0);
                a[1] = pack_scale14(f1);
                a[2] = pack_scale14(f2);
                a[3] = pack_scale14(f3);
            }
            const char* bp = Bs + kk * 2048 + lane * 16;
            uint4 b01 = *(const uint4*)(bp);
            uint4 b23 = *(const uint4*)(bp + 512);
            uint4 b45 = *(const uint4*)(bp + 1024);
            uint4 b67 = *(const uint4*)(bp + 1536);
            mma_f16(d[0], a, b01.x, b01.y);
            mma_f16(d[1], a, b01.z, b01.w);
            mma_f16(d[2], a, b23.x, b23.y);
            mma_f16(d[3], a, b23.z, b23.w);
            mma_f16(d[4], a, b45.x, b45.y);
            mma_f16(d[5], a, b45.z, b45.w);
            mma_f16(d[6], a, b67.x, b67.y);
            mma_f16(d[7], a, b67.z, b67.w);
        }
        if (++s == NSTAGE) s = 0;
    }

    // store raw (still x2^14-scaled) partials; K2b de-scales.
    float* base = g_part + (size_t)ks * NNODES * NHID;
    int r0 = row0 + w * 16 + g;
#pragma unroll
    for (int ni = 0; ni < 8; ni++) {
        int col = ni * 8 + 2 * t;
        *(float2*)(base + (size_t)r0 * NHID + col)       = make_float2(d[ni][0], d[ni][1]);
        *(float2*)(base + (size_t)(r0 + 8) * NHID + col) = make_float2(d[ni][2], d[ni][3]);
    }
}

// ============================ K2b: reduce + relu + @W2 =====================
__global__ __launch_bounds__(256) void k2b_reduce(const float* __restrict__ b1,
                                                  const float* __restrict__ W2) {
    __shared__ float sb1[64], sW2[128];
    int tid = threadIdx.x;
    if (tid < 64) sb1[tid] = b1[tid];
    if (tid < 128) sW2[tid] = W2[tid];
    __syncthreads();

    int row = blockIdx.x * 256 + tid;
    const float4* p0 = (const float4*)(g_part + (size_t)row * NHID);
    const float4* p1 = (const float4*)(g_part + (size_t)(NNODES + row) * NHID);
    const float4* p2 = (const float4*)(g_part + (size_t)(2 * NNODES + row) * NHID);
    const float4* p3 = (const float4*)(g_part + (size_t)(3 * NNODES + row) * NHID);

    float a0 = 0.f, a1 = 0.f;
#pragma unroll
    for (int c4 = 0; c4 < 16; c4++) {
        float4 v0 = p0[c4], v1 = p1[c4], v2 = p2[c4], v3 = p3[c4];
        float sv[4] = {v0.x + v1.x + v2.x + v3.x, v0.y + v1.y + v2.y + v3.y,
                       v0.z + v1.z + v2.z + v3.z, v0.w + v1.w + v2.w + v3.w};
#pragma unroll
        for (int e = 0; e < 4; e++) {
            int col = c4 * 4 + e;
            float h = fmaxf(fmaf(sv[e], SCALE_INV, sb1[col]), 0.f);
            a0 = fmaf(h, sW2[2 * col + 0], a0);
            a1 = fmaf(h, sW2[2 * col + 1], a1);
        }
    }
    g_hw2[2 * row + 0] = a0;
    g_hw2[2 * row + 1] = a1;
}

// ============================ K3: adj @ hw2 + b2 ===========================
// No smem: hw2 via __ldg (L1/L2-resident), adj streamed __ldcs.
// 16 rows/CTA (2 rows/warp), grid 1024, 4 CTAs/SM -> 32 warps/SM of MLP.
__global__ __launch_bounds__(256, 4) void k3_spmv(const float* __restrict__ adj,
                                                  const float* __restrict__ b2) {
    int tid = threadIdx.x;
    int wid = tid >> 5, lane = tid & 31;
    int r0 = blockIdx.x * 16 + wid * 2;
    const float4* ap0 = (const float4*)(adj + (size_t)(r0 + 0) * NNODES);
    const float4* ap1 = (const float4*)(adj + (size_t)(r0 + 1) * NNODES);
    const float4* hp  = (const float4*)g_hw2;

    float acc00 = 0.f, acc01 = 0.f, acc10 = 0.f, acc11 = 0.f;

#pragma unroll 1
    for (int q = lane; q < NNODES / 4; q += 64) {
        float4 a00 = __ldcs(ap0 + q);
        float4 a10 = __ldcs(ap1 + q);
        float4 a01 = __ldcs(ap0 + q + 32);
        float4 a11 = __ldcs(ap1 + q + 32);
        float4 h0a = __ldg(hp + 2 * q);
        float4 h0b = __ldg(hp + 2 * q + 1);
        float4 h1a = __ldg(hp + 2 * (q + 32));
        float4 h1b = __ldg(hp + 2 * (q + 32) + 1);

        acc00 = fmaf(a00.x, h0a.x, acc00);
        acc01 = fmaf(a00.x, h0a.y, acc01);
        acc10 = fmaf(a10.x, h0a.x, acc10);
        acc11 = fmaf(a10.x, h0a.y, acc11);
        acc00 = fmaf(a00.y, h0a.z, acc00);
        acc01 = fmaf(a00.y, h0a.w, acc01);
        acc10 = fmaf(a10.y, h0a.z, acc10);
        acc11 = fmaf(a10.y, h0a.w, acc11);
        acc00 = fmaf(a00.z, h0b.x, acc00);
        acc01 = fmaf(a00.z, h0b.y, acc01);
        acc10 = fmaf(a10.z, h0b.x, acc10);
        acc11 = fmaf(a10.z, h0b.y, acc11);
        acc00 = fmaf(a00.w, h0b.z, acc00);
        acc01 = fmaf(a00.w, h0b.w, acc01);
        acc10 = fmaf(a10.w, h0b.z, acc10);
        acc11 = fmaf(a10.w, h0b.w, acc11);

        acc00 = fmaf(a01.x, h1a.x, acc00);
        acc01 = fmaf(a01.x, h1a.y, acc01);
        acc10 = fmaf(a11.x, h1a.x, acc10);
        acc11 = fmaf(a11.x, h1a.y, acc11);
        acc00 = fmaf(a01.y, h1a.z, acc00);
        acc01 = fmaf(a01.y, h1a.w, acc01);
        acc10 = fmaf(a11.y, h1a.z, acc10);
        acc11 = fmaf(a11.y, h1a.w, acc11);
        acc00 = fmaf(a01.z, h1b.x, acc00);
        acc01 = fmaf(a01.z, h1b.y, acc01);
        acc10 = fmaf(a11.z, h1b.x, acc10);
        acc11 = fmaf(a11.z, h1b.y, acc11);
        acc00 = fmaf(a01.w, h1b.z, acc00);
        acc01 = fmaf(a01.w, h1b.w, acc01);
        acc10 = fmaf(a11.w, h1b.z, acc10);
        acc11 = fmaf(a11.w, h1b.w, acc11);
    }

#pragma unroll
    for (int sft = 16; sft; sft >>= 1) {
        acc00 += __shfl_xor_sync(0xffffffffu, acc00, sft);
        acc01 += __shfl_xor_sync(0xffffffffu, acc01, sft);
        acc10 += __shfl_xor_sync(0xffffffffu, acc10, sft);
        acc11 += __shfl_xor_sync(0xffffffffu, acc11, sft);
    }
    if (lane == 0) {
        float bb0 = b2[0], bb1 = b2[1];
        g_h2[2 * r0 + 0] = acc00 + bb0;
        g_h2[2 * r0 + 1] = acc01 + bb1;
        g_h2[2 * r0 + 2] = acc10 + bb0;
        g_h2[2 * r0 + 3] = acc11 + bb1;
    }
}

// ============================ K4: max-pool + linear ========================
__global__ __launch_bounds__(1024) void k4_final(const float* __restrict__ W3,
                                                 const float* __restrict__ b3,
                                                 float* __restrict__ out) {
    __shared__ float s0[1024], s1[1024];
    int tid = threadIdx.x;
    float m0 = -3.4e38f, m1 = -3.4e38f;
#pragma unroll
    for (int it = 0; it < NNODES / 1024; it++) {
        float2 v = *(const float2*)(g_h2 + 2 * (it * 1024 + tid));
        m0 = fmaxf(m0, v.x);
        m1 = fmaxf(m1, v.y);
    }
    s0[tid] = m0; s1[tid] = m1;
    __syncthreads();
#pragma unroll
    for (int s = 512; s; s >>= 1) {
        if (tid < s) {
            s0[tid] = fmaxf(s0[tid], s0[tid + s]);
            s1[tid] = fmaxf(s1[tid], s1[tid + s]);
        }
        __syncthreads();
    }
    if (tid == 0) out[0] = s0[0] * W3[0] + s1[0] * W3[1] + b3[0];
}

// ============================ launch =======================================
extern "C" void kernel_launch(void* const* d_in, const int* in_sizes, int n_in,
                              void* d_out, int out_size) {
    const float* x   = (const float*)d_in[0];
    const float* adj = (const float*)d_in[1];
    const float* W1  = (const float*)d_in[2];
    const float* b1  = (const float*)d_in[3];
    const float* W2  = (const float*)d_in[4];
    const float* b2  = (const float*)d_in[5];
    const float* W3  = (const float*)d_in[6];
    const float* b3  = (const float*)d_in[7];
    float* out = (float*)d_out;

    (void)in_sizes; (void)n_in; (void)out_size;

    cudaFuncSetAttribute(k1_xw1t, cudaFuncAttributeMaxDynamicSharedMemorySize, 131072);
    cudaFuncSetAttribute(k2_gemm, cudaFuncAttributeMaxDynamicSharedMemorySize, K2_SMEM);

    // two dummies put ncu's capture slot (our 4th launch) on k2_gemm
    k_dummy<<<1, 32>>>();
    k_dummy<<<1, 32>>>();
    k1_xw1t<<<NNODES / 64, 256, 131072>>>(x, W1);
    k2_gemm<<<256 * KSPLIT, 128, K2_SMEM>>>(adj);
    k2b_reduce<<<NNODES / 256, 256>>>(b1, W2);
    k3_spmv<<<NNODES / 16, 256>>>(adj, b2);
    k4_final<<<1, 1024>>>(W3, b3, out);
}

// round 16
// speedup vs baseline: 1.4338x; 1.0387x over previous
#include <cuda_runtime.h>
#include <cuda_bf16.h>
#include <cuda_fp16.h>
#include <cstdint>

// ============================ problem constants ============================
#define NNODES 16384
#define NFEAT  256
#define NHID   64
#define KSPLIT 4
#define KSEG   (NNODES / KSPLIT)   /* 4096 */

// ============================ scratch (device globals) =====================
// XW1^T in mma.sync fragment order:
//   [kg = k/16][ni4 = ni/2][lane][16B], 2 KB per kg, 2 MB total.
__device__ __align__(1024) __half g_xw1f[NHID * NNODES];
__device__ __align__(1024) float  g_part[KSPLIT * NNODES * NHID];  // K-split partials (16 MB)
__device__ __align__(256)  float  g_hw2[NNODES * 2];
__device__ __align__(256)  float  g_h2[NNODES * 2];

// ============================ PTX helpers (base-target only) ===============
__device__ __forceinline__ uint32_t smem_u32(const void* p) {
    uint32_t a;
    asm("{ .reg .u64 t; cvta.to.shared.u64 t, %1; cvt.u32.u64 %0, t; }" : "=r"(a) : "l"(p));
    return a;
}

#define CP_ASYNC16(dst_u32, src_ptr) \
    asm volatile("cp.async.cg.shared.global [%0], [%1], 16;" \
                 :: "r"(dst_u32), "l"(src_ptr) : "memory")
#define CP_COMMIT()  asm volatile("cp.async.commit_group;" ::: "memory")
#define CP_WAIT_1()  asm volatile("cp.async.wait_group 1;" ::: "memory")

// fp16 MMA m16n8k16, fp32 accumulate (base-target sm_80+)
__device__ __forceinline__ void mma_f16(float* d, const uint32_t* a, uint32_t b0, uint32_t b1) {
    asm volatile(
        "mma.sync.aligned.m16n8k16.row.col.f32.f16.f16.f32 "
        "{%0,%1,%2,%3}, {%4,%5,%6,%7}, {%8,%9}, {%0,%1,%2,%3};"
        : "+f"(d[0]), "+f"(d[1]), "+f"(d[2]), "+f"(d[3])
        : "r"(a[0]), "r"(a[1]), "r"(a[2]), "r"(a[3]), "r"(b0), "r"(b1));
}

// scale float2 by 2^14 (exact integer exponent add; adj >= 0) and pack to half2.
__device__ __forceinline__ uint32_t pack_scale14(float2 f) {
    float x = __uint_as_float(__float_as_uint(f.x) + (14u << 23));
    float y = __uint_as_float(__float_as_uint(f.y) + (14u << 23));
    __half2 h = __floats2half2_rn(x, y);
    return *(uint32_t*)&h;
}
#define SCALE_INV 6.103515625e-05f   /* 2^-14, exact */

// ============================ K0: dummy (ncu slot alignment) ===============
__global__ void k_dummy() {}

// ============================ K1: XW1^T -> fragment layout =================
__global__ __launch_bounds__(256) void k1_xw1t(const float* __restrict__ x,
                                               const float* __restrict__ W1) {
    extern __shared__ float sm1[];
    float* xs = sm1;              // [64][256]
    float* ws = sm1 + 64 * 256;   // [256][64]
    int tid = threadIdx.x;
    int node0 = blockIdx.x * 64;

    const float4* xsrc = (const float4*)(x + (size_t)node0 * NFEAT);
    float4* xdst = (float4*)xs;
#pragma unroll
    for (int j = 0; j < 16; j++) xdst[tid + j * 256] = xsrc[tid + j * 256];
    const float4* wsrc = (const float4*)W1;
    float4* wdst = (float4*)ws;
#pragma unroll
    for (int j = 0; j < 16; j++) wdst[tid + j * 256] = wsrc[tid + j * 256];
    __syncthreads();

    int i0 = (tid >> 4) * 4;
    int n0 = (tid & 15) * 4;
    float acc[4][4];
#pragma unroll
    for (int a = 0; a < 4; a++)
#pragma unroll
        for (int b = 0; b < 4; b++) acc[a][b] = 0.f;

#pragma unroll 4
    for (int f = 0; f < NFEAT; f++) {
        float4 w = *(const float4*)(ws + f * 64 + n0);
#pragma unroll
        for (int ii = 0; ii < 4; ii++) {
            float xv = xs[(i0 + ii) * NFEAT + f];
            acc[ii][0] = fmaf(xv, w.x, acc[ii][0]);
            acc[ii][1] = fmaf(xv, w.y, acc[ii][1]);
            acc[ii][2] = fmaf(xv, w.z, acc[ii][2]);
            acc[ii][3] = fmaf(xv, w.w, acc[ii][3]);
        }
    }
    // scatter into fragment layout
    char* fb = (char*)g_xw1f;
#pragma unroll
    for (int jj = 0; jj < 4; jj++) {
        int h = n0 + jj;              // hid (B row n)
        int g = h & 7, ni = h >> 3;
#pragma unroll
        for (int ii = 0; ii < 4; ii++) {
            int k = node0 + i0 + ii;  // node (B col k)
            int kg = k >> 4, k16 = k & 15;
            int reg = k16 >> 3, rem = k16 & 7, t = rem >> 1, hf = rem & 1;
            size_t off = (size_t)kg * 2048 + (size_t)(ni >> 1) * 512 +
                         (size_t)(g * 4 + t) * 16 + (ni & 1) * 8 + reg * 4 + hf * 2;
            *(__half*)(fb + off) = __float2half_rn(acc[ii][jj]);
        }
    }
}

// ============================ K2: main GEMM, K-split x4 ====================
// CTA: 128 threads, tile M=64, K=4096 -> grid 1024.
// BK=64, NSTAGE=3 (2 in flight) -> 76.8 KB/CTA -> 3 CTAs/SM = 12 warps/SM.
#define BK        64
#define A_PAD     68                         /* fp32 per A row */
#define A_BYTES   (64 * A_PAD * 4)           /* 17408 */
#define B_BYTES   8192                       /* 4 kg x 2 KB, contiguous */
#define NSTAGE    3
#define STAGE_BYTES (A_BYTES + B_BYTES)      /* 25600 */
#define K2_SMEM   (NSTAGE * STAGE_BYTES)     /* 76800 */
#define NITER     (KSEG / BK)                /* 64 */

__device__ __forceinline__ void k2_load_stage(const float* __restrict__ adj, int row0,
                                              int s, int k0, char* smem, int tid) {
    float* As = (float*)(smem + s * STAGE_BYTES);
    char*  Bs = smem + s * STAGE_BYTES + A_BYTES;
#pragma unroll
    for (int j = 0; j < 8; j++) {          // A: 64x64 fp32 = 2048 float4
        int sl = tid + j * 128;
        int row = sl >> 4, c = sl & 15;
        CP_ASYNC16(smem_u32(As + row * A_PAD + c * 4),
                   adj + (size_t)(row0 + row) * NNODES + k0 + c * 4);
    }
    const char* bsrc = (const char*)g_xw1f + (size_t)k0 * 128;   // k0/16 * 2048
#pragma unroll
    for (int j = 0; j < 4; j++) {          // B: 8 KB contiguous = 512 chunks
        int sl = tid + j * 128;
        CP_ASYNC16(smem_u32(Bs + sl * 16), bsrc + sl * 16);
    }
}

__global__ __launch_bounds__(128, 3) void k2_gemm(const float* __restrict__ adj) {
    extern __shared__ char smem[];
    int tid = threadIdx.x;
    int lane = tid & 31;
    int w = tid >> 5;           // 0..3
    int g = lane >> 2;          // 0..7
    int t = lane & 3;           // 0..3
    int m0 = blockIdx.x & 255;  // M-tile (64 rows)
    int ks = blockIdx.x >> 8;   // K-split 0..3
    int row0 = m0 * 64;
    int kbase = ks * KSEG;

    float d[8][4];
#pragma unroll
    for (int ni = 0; ni < 8; ni++)
#pragma unroll
        for (int c = 0; c < 4; c++) d[ni][c] = 0.f;

    k2_load_stage(adj, row0, 0, kbase, smem, tid);      CP_COMMIT();
    k2_load_stage(adj, row0, 1, kbase + BK, smem, tid); CP_COMMIT();

    int s = 0;
#pragma unroll 1
    for (int i = 0; i < NITER; i++) {
        CP_WAIT_1();       // group i complete (<=1 newer group pending)
        __syncthreads();   // all warps see stage i; stage (i+2)%3 free for reuse

        if (i + 2 < NITER) {
            int sn = s + 2; if (sn >= NSTAGE) sn -= NSTAGE;
            k2_load_stage(adj, row0, sn, kbase + (i + 2) * BK, smem, tid);
        }
        CP_COMMIT();       // one group per iter keeps wait_group counting uniform

        const float* As = (const float*)(smem + s * STAGE_BYTES);
        const char* Bs = smem + s * STAGE_BYTES + A_BYTES;
#pragma unroll
        for (int kk = 0; kk < 4; kk++) {
            int kb = kk * 16;
            uint32_t a[4];
            {
                const float* ap = As + (w * 16 + g) * A_PAD + kb + 2 * t;
                float2 f0 = *(const float2*)(ap);
                float2 f1 = *(const float2*)(ap + 8 * A_PAD);
                float2 f2 = *(const float2*)(ap + 8);
                float2 f3 = *(const float2*)(ap + 8 * A_PAD + 8);
                a[0] = pack_scale14(f0);
                a[1] = pack_scale14(f1);
                a[2] = pack_scale14(f2);
                a[3] = pack_scale14(f3);
            }
            const char* bp = Bs + kk * 2048 + lane * 16;
            uint4 b01 = *(const uint4*)(bp);
            uint4 b23 = *(const uint4*)(bp + 512);
            uint4 b45 = *(const uint4*)(bp + 1024);
            uint4 b67 = *(const uint4*)(bp + 1536);
            mma_f16(d[0], a, b01.x, b01.y);
            mma_f16(d[1], a, b01.z, b01.w);
            mma_f16(d[2], a, b23.x, b23.y);
            mma_f16(d[3], a, b23.z, b23.w);
            mma_f16(d[4], a, b45.x, b45.y);
            mma_f16(d[5], a, b45.z, b45.w);
            mma_f16(d[6], a, b67.x, b67.y);
            mma_f16(d[7], a, b67.z, b67.w);
        }
        if (++s == NSTAGE) s = 0;
    }

    // store raw (still x2^14-scaled) partials; K2b de-scales.
    float* base = g_part + (size_t)ks * NNODES * NHID;
    int r0 = row0 + w * 16 + g;
#pragma unroll
    for (int ni = 0; ni < 8; ni++) {
        int col = ni * 8 + 2 * t;
        *(float2*)(base + (size_t)r0 * NHID + col)       = make_float2(d[ni][0], d[ni][1]);
        *(float2*)(base + (size_t)(r0 + 8) * NHID + col) = make_float2(d[ni][2], d[ni][3]);
    }
}

// ============================ K2b: reduce + relu + @W2 =====================
__global__ __launch_bounds__(256) void k2b_reduce(const float* __restrict__ b1,
                                                  const float* __restrict__ W2) {
    __shared__ float sb1[64], sW2[128];
    int tid = threadIdx.x;
    if (tid < 64) sb1[tid] = b1[tid];
    if (tid < 128) sW2[tid] = W2[tid];
    __syncthreads();

    int row = blockIdx.x * 256 + tid;
    const float4* p0 = (const float4*)(g_part + (size_t)row * NHID);
    const float4* p1 = (const float4*)(g_part + (size_t)(NNODES + row) * NHID);
    const float4* p2 = (const float4*)(g_part + (size_t)(2 * NNODES + row) * NHID);
    const float4* p3 = (const float4*)(g_part + (size_t)(3 * NNODES + row) * NHID);

    float a0 = 0.f, a1 = 0.f;
#pragma unroll
    for (int c4 = 0; c4 < 16; c4++) {
        float4 v0 = p0[c4], v1 = p1[c4], v2 = p2[c4], v3 = p3[c4];
        float sv[4] = {v0.x + v1.x + v2.x + v3.x, v0.y + v1.y + v2.y + v3.y,
                       v0.z + v1.z + v2.z + v3.z, v0.w + v1.w + v2.w + v3.w};
#pragma unroll
        for (int e = 0; e < 4; e++) {
            int col = c4 * 4 + e;
            float h = fmaxf(fmaf(sv[e], SCALE_INV, sb1[col]), 0.f);
            a0 = fmaf(h, sW2[2 * col + 0], a0);
            a1 = fmaf(h, sW2[2 * col + 1], a1);
        }
    }
    g_hw2[2 * row + 0] = a0;
    g_hw2[2 * row + 1] = a1;
}

// ============================ K3: adj @ hw2 + b2 ===========================
// No smem: hw2 via __ldg (L1/L2-resident), adj streamed __ldcs.
// 16 rows/CTA (2 rows/warp), grid 1024, 4 CTAs/SM -> 32 warps/SM of MLP.
__global__ __launch_bounds__(256, 4) void k3_spmv(const float* __restrict__ adj,
                                                  const float* __restrict__ b2) {
    int tid = threadIdx.x;
    int wid = tid >> 5, lane = tid & 31;
    int r0 = blockIdx.x * 16 + wid * 2;
    const float4* ap0 = (const float4*)(adj + (size_t)(r0 + 0) * NNODES);
    const float4* ap1 = (const float4*)(adj + (size_t)(r0 + 1) * NNODES);
    const float4* hp  = (const float4*)g_hw2;

    float acc00 = 0.f, acc01 = 0.f, acc10 = 0.f, acc11 = 0.f;

#pragma unroll 1
    for (int q = lane; q < NNODES / 4; q += 64) {
        float4 a00 = __ldcs(ap0 + q);
        float4 a10 = __ldcs(ap1 + q);
        float4 a01 = __ldcs(ap0 + q + 32);
        float4 a11 = __ldcs(ap1 + q + 32);
        float4 h0a = __ldg(hp + 2 * q);
        float4 h0b = __ldg(hp + 2 * q + 1);
        float4 h1a = __ldg(hp + 2 * (q + 32));
        float4 h1b = __ldg(hp + 2 * (q + 32) + 1);

        acc00 = fmaf(a00.x, h0a.x, acc00);
        acc01 = fmaf(a00.x, h0a.y, acc01);
        acc10 = fmaf(a10.x, h0a.x, acc10);
        acc11 = fmaf(a10.x, h0a.y, acc11);
        acc00 = fmaf(a00.y, h0a.z, acc00);
        acc01 = fmaf(a00.y, h0a.w, acc01);
        acc10 = fmaf(a10.y, h0a.z, acc10);
        acc11 = fmaf(a10.y, h0a.w, acc11);
        acc00 = fmaf(a00.z, h0b.x, acc00);
        acc01 = fmaf(a00.z, h0b.y, acc01);
        acc10 = fmaf(a10.z, h0b.x, acc10);
        acc11 = fmaf(a10.z, h0b.y, acc11);
        acc00 = fmaf(a00.w, h0b.z, acc00);
        acc01 = fmaf(a00.w, h0b.w, acc01);
        acc10 = fmaf(a10.w, h0b.z, acc10);
        acc11 = fmaf(a10.w, h0b.w, acc11);

        acc00 = fmaf(a01.x, h1a.x, acc00);
        acc01 = fmaf(a01.x, h1a.y, acc01);
        acc10 = fmaf(a11.x, h1a.x, acc10);
        acc11 = fmaf(a11.x, h1a.y, acc11);
        acc00 = fmaf(a01.y, h1a.z, acc00);
        acc01 = fmaf(a01.y, h1a.w, acc01);
        acc10 = fmaf(a11.y, h1a.z, acc10);
        acc11 = fmaf(a11.y, h1a.w, acc11);
        acc00 = fmaf(a01.z, h1b.x, acc00);
        acc01 = fmaf(a01.z, h1b.y, acc01);
        acc10 = fmaf(a11.z, h1b.x, acc10);
        acc11 = fmaf(a11.z, h1b.y, acc11);
        acc00 = fmaf(a01.w, h1b.z, acc00);
        acc01 = fmaf(a01.w, h1b.w, acc01);
        acc10 = fmaf(a11.w, h1b.z, acc10);
        acc11 = fmaf(a11.w, h1b.w, acc11);
    }

#pragma unroll
    for (int sft = 16; sft; sft >>= 1) {
        acc00 += __shfl_xor_sync(0xffffffffu, acc00, sft);
        acc01 += __shfl_xor_sync(0xffffffffu, acc01, sft);
        acc10 += __shfl_xor_sync(0xffffffffu, acc10, sft);
        acc11 += __shfl_xor_sync(0xffffffffu, acc11, sft);
    }
    if (lane == 0) {
        float bb0 = b2[0], bb1 = b2[1];
        g_h2[2 * r0 + 0] = acc00 + bb0;
        g_h2[2 * r0 + 1] = acc01 + bb1;
        g_h2[2 * r0 + 2] = acc10 + bb0;
        g_h2[2 * r0 + 3] = acc11 + bb1;
    }
}

// ============================ K4: max-pool + linear ========================
__global__ __launch_bounds__(1024) void k4_final(const float* __restrict__ W3,
                                                 const float* __restrict__ b3,
                                                 float* __restrict__ out) {
    __shared__ float s0[1024], s1[1024];
    int tid = threadIdx.x;
    float m0 = -3.4e38f, m1 = -3.4e38f;
#pragma unroll
    for (int it = 0; it < NNODES / 1024; it++) {
        float2 v = *(const float2*)(g_h2 + 2 * (it * 1024 + tid));
        m0 = fmaxf(m0, v.x);
        m1 = fmaxf(m1, v.y);
    }
    s0[tid] = m0; s1[tid] = m1;
    __syncthreads();
#pragma unroll
    for (int s = 512; s; s >>= 1) {
        if (tid < s) {
            s0[tid] = fmaxf(s0[tid], s0[tid + s]);
            s1[tid] = fmaxf(s1[tid], s1[tid + s]);
        }
        __syncthreads();
    }
    if (tid == 0) out[0] = s0[0] * W3[0] + s1[0] * W3[1] + b3[0];
}

// ============================ launch =======================================
extern "C" void kernel_launch(void* const* d_in, const int* in_sizes, int n_in,
                              void* d_out, int out_size) {
    const float* x   = (const float*)d_in[0];
    const float* adj = (const float*)d_in[1];
    const float* W1  = (const float*)d_in[2];
    const float* b1  = (const float*)d_in[3];
    const float* W2  = (const float*)d_in[4];
    const float* b2  = (const float*)d_in[5];
    const float* W3  = (const float*)d_in[6];
    const float* b3  = (const float*)d_in[7];
    float* out = (float*)d_out;

    (void)in_sizes; (void)n_in; (void)out_size;

    cudaFuncSetAttribute(k1_xw1t, cudaFuncAttributeMaxDynamicSharedMemorySize, 131072);
    cudaFuncSetAttribute(k2_gemm, cudaFuncAttributeMaxDynamicSharedMemorySize, K2_SMEM);

    // two dummies put ncu's capture slot (our 4th launch) on k2_gemm
    k_dummy<<<1, 32>>>();
    k_dummy<<<1, 32>>>();
    k1_xw1t<<<NNODES / 64, 256, 131072>>>(x, W1);
    k2_gemm<<<256 * KSPLIT, 128, K2_SMEM>>>(adj);
    k2b_reduce<<<NNODES / 256, 256>>>(b1, W2);
    k3_spmv<<<NNODES / 16, 256>>>(adj, b2);
    k4_final<<<1, 1024>>>(W3, b3, out);
}